// round 7
// baseline (speedup 1.0000x reference)
#include <cuda_runtime.h>
#include <cuda_bf16.h>
#include <cstdint>

// ---------------------------------------------------------------------------
// Problem constants
// ---------------------------------------------------------------------------
#define IN_F    4096
#define OUT_F   16384
#define ACT_IN  2048
#define ACT_OUT 8192
#define NROWS   8192      // B*S

// GEMM tiling: CTA 256(M) x 128(N), 8 warps as 4(M) x 2(N), warp tile 64x64
#define BM 256
#define BN 128
#define KC 64                    // K elements per stage (128 B/row in smem)
#define NSTAGE (ACT_IN / KC)     // 32
#define NTH 256

// SMEM per stage: Ah 32K | Al 32K | Bh 16K | Bl 16K = 96 KB; 2 stages = 192 KB
#define T_AH 0
#define T_AL 32768
#define T_BH 65536
#define T_BL 81920
#define STAGE_BYTES 98304
#define SMEM_TOTAL  196608

// bf16-split operand scratch (allocation-free rule: __device__ globals)
__device__ __nv_bfloat16 g_Ah[(size_t)NROWS * ACT_IN];
__device__ __nv_bfloat16 g_Al[(size_t)NROWS * ACT_IN];
__device__ __nv_bfloat16 g_Bh[(size_t)ACT_OUT * ACT_IN];
__device__ __nv_bfloat16 g_Bl[(size_t)ACT_OUT * ACT_IN];

// ---------------------------------------------------------------------------
// PTX helpers (sm_80-baseline only — harness lowers through plain compute_103)
// ---------------------------------------------------------------------------
__device__ __forceinline__ uint32_t smem_u32(const void* p) {
    uint32_t a;
    asm("{ .reg .u64 t; cvta.to.shared.u64 t, %1; cvt.u32.u64 %0, t; }"
        : "=r"(a) : "l"(p));
    return a;
}

#define SWZ(o) ((o) ^ (((o) >> 3) & 0x70))   // SW128 xor swizzle (16B granules)

#define CPA16(sa, gp) \
    asm volatile("cp.async.cg.shared.global [%0], [%1], 16;" :: "r"(sa), "l"(gp) : "memory")
#define CPA_COMMIT() asm volatile("cp.async.commit_group;" ::: "memory")
#define CPA_WAIT(n)  asm volatile("cp.async.wait_group %0;" :: "n"(n) : "memory")

#define LDSM4(r0, r1, r2, r3, a) \
    asm volatile("ldmatrix.sync.aligned.m8n8.x4.shared.b16 {%0,%1,%2,%3}, [%4];" \
                 : "=r"(r0), "=r"(r1), "=r"(r2), "=r"(r3) : "r"(a))

// D += A*B, bf16 in, fp32 accum.  A frag 4xb32, B frag 2xb32, C 4xf32.
#define MMA(c, a0, a1, a2, a3, b0, b1) \
    asm volatile("mma.sync.aligned.m16n8k16.row.col.f32.bf16.bf16.f32 " \
                 "{%0,%1,%2,%3}, {%4,%5,%6,%7}, {%8,%9}, {%0,%1,%2,%3};" \
                 : "+f"((c)[0]), "+f"((c)[1]), "+f"((c)[2]), "+f"((c)[3]) \
                 : "r"(a0), "r"(a1), "r"(a2), "r"(a3), "r"(b0), "r"(b1))

// ---------------------------------------------------------------------------
// Pre-pass 1: gather active input cols + split fp32 -> bf16 hi/lo
// ---------------------------------------------------------------------------
__global__ void nsl_split_x(const float* __restrict__ x,
                            const int* __restrict__ in_idx) {
    const int k = blockIdx.x * blockDim.x + threadIdx.x;
    const int m = blockIdx.y;
    const int c = __ldg(&in_idx[k]);
    const float v = __ldg(&x[(size_t)m * IN_F + c]);
    const __nv_bfloat16 h = __float2bfloat16(v);
    const __nv_bfloat16 l = __float2bfloat16(v - __bfloat162float(h));
    g_Ah[(size_t)m * ACT_IN + k] = h;
    g_Al[(size_t)m * ACT_IN + k] = l;
}

// Pre-pass 2: split weight fp32 -> bf16 hi/lo
__global__ void nsl_split_w(const float* __restrict__ w) {
    const size_t i = blockIdx.x * (size_t)blockDim.x + threadIdx.x;
    const float v = __ldg(&w[i]);
    const __nv_bfloat16 h = __float2bfloat16(v);
    const __nv_bfloat16 l = __float2bfloat16(v - __bfloat162float(h));
    g_Bh[i] = h;
    g_Bl[i] = l;
}

// ---------------------------------------------------------------------------
// Main GEMM: C[m, out_idx[n]] = sum_k (Ah+Al)[m,k]*(Bh+Bl)[n,k] + bias[n]
// 3 HMMA products (AhBh + AhBl + AlBh), fp32 register accumulation.
// ---------------------------------------------------------------------------
__global__ __launch_bounds__(NTH, 1)
void nsl_mma(const float* __restrict__ bias,
             const int*   __restrict__ out_idx,
             float*       __restrict__ out) {
    extern __shared__ __align__(1024) char smem[];
    const uint32_t sb = smem_u32(smem);
    const int tid  = threadIdx.x;
    const int wid  = tid >> 5;
    const int lane = tid & 31;
    const int m0 = blockIdx.y * BM;
    const int n0 = blockIdx.x * BN;

    const int warp_m = wid >> 1;       // 0..3  -> 64-row slab of M
    const int warp_n = wid & 1;        // 0..1  -> 64-col slab of N

    // ---- cp.async slot mapping ----
    // A tile: 256 rows x 8 x 16B = 2048 chunks -> 8/thread
    // B tile: 128 rows x 8 x 16B = 1024 chunks -> 4/thread
    int aG[8]; uint32_t aS[8];
    int bG[4]; uint32_t bS[4];
#pragma unroll
    for (int i = 0; i < 8; i++) {
        const int id = tid + i * NTH;
        const int r = id >> 3, cv = id & 7;
        aG[i] = r * ACT_IN + cv * 8;
        aS[i] = SWZ((uint32_t)(r * 128 + cv * 16));
    }
#pragma unroll
    for (int i = 0; i < 4; i++) {
        const int id = tid + i * NTH;
        const int r = id >> 3, cv = id & 7;
        bG[i] = r * ACT_IN + cv * 8;
        bS[i] = SWZ((uint32_t)(r * 128 + cv * 16));
    }
    const __nv_bfloat16* pAh = g_Ah + (size_t)m0 * ACT_IN;
    const __nv_bfloat16* pAl = g_Al + (size_t)m0 * ACT_IN;
    const __nv_bfloat16* pBh = g_Bh + (size_t)n0 * ACT_IN;
    const __nv_bfloat16* pBl = g_Bl + (size_t)n0 * ACT_IN;

    auto load_stage = [&](int s, int b) {
        const uint32_t base = sb + b * STAGE_BYTES;
        const int ke = s * KC;
#pragma unroll
        for (int i = 0; i < 8; i++) {
            CPA16(base + T_AH + aS[i], pAh + ke + aG[i]);
            CPA16(base + T_AL + aS[i], pAl + ke + aG[i]);
        }
#pragma unroll
        for (int i = 0; i < 4; i++) {
            CPA16(base + T_BH + bS[i], pBh + ke + bG[i]);
            CPA16(base + T_BL + bS[i], pBl + ke + bG[i]);
        }
        CPA_COMMIT();
    };

    // ---- ldmatrix lane addressing ----
    // lane -> row lrow (0..15), k-half lkoff (0 or 16 bytes).
    // SWZ(row*128 + kb) = row*128 + (((row&7)<<4) ^ kb)  since kb < 128.
    const int lrow  = lane & 15;
    const uint32_t lkoff = (uint32_t)((lane >> 4) * 16);

    // Per-m-tile A row bases (swizzle xor folded per lane), tile-local bytes
    uint32_t aBase[4];
#pragma unroll
    for (int mt = 0; mt < 4; mt++) {
        const int row = warp_m * 64 + mt * 16 + lrow;
        aBase[mt] = (uint32_t)(row * 128) + (((uint32_t)(row & 7)) << 4);
    }
    // Per-n-group B row bases (4 groups of n16)
    uint32_t bBase[4];
#pragma unroll
    for (int g = 0; g < 4; g++) {
        const int row = warp_n * 64 + g * 16 + lrow;
        bBase[g] = (uint32_t)(row * 128) + (((uint32_t)(row & 7)) << 4);
    }

    // ---- accumulators: 4 m-tiles x 8 n8-tiles x 4 f32 = 128 regs ----
    float acc[4][8][4];
#pragma unroll
    for (int i = 0; i < 4; i++)
#pragma unroll
        for (int j = 0; j < 8; j++)
#pragma unroll
            for (int q = 0; q < 4; q++) acc[i][j][q] = 0.0f;

    // ---- pipeline prologue ----
    load_stage(0, 0);
    load_stage(1, 1);

    for (int s = 0; s < NSTAGE; s++) {
        if (s < NSTAGE - 1) { CPA_WAIT(1); } else { CPA_WAIT(0); }
        __syncthreads();

        const uint32_t base = sb + (s & 1) * STAGE_BYTES;

#pragma unroll
        for (int ks = 0; ks < 4; ks++) {
            const uint32_t kb = (uint32_t)(ks * 32) + lkoff;  // ^ with folded bases

            // A fragments for this k16: hi and lo, all 4 m-tiles (32 regs)
            uint32_t ah[4][4], al[4][4];
#pragma unroll
            for (int mt = 0; mt < 4; mt++)
                LDSM4(ah[mt][0], ah[mt][1], ah[mt][2], ah[mt][3],
                      base + T_AH + (aBase[mt] ^ kb));
#pragma unroll
            for (int mt = 0; mt < 4; mt++)
                LDSM4(al[mt][0], al[mt][1], al[mt][2], al[mt][3],
                      base + T_AL + (aBase[mt] ^ kb));

            // Stream B in 4 groups of n16 (bh/bl transient: 8 regs live)
#pragma unroll
            for (int g = 0; g < 4; g++) {
                uint32_t bh0, bh1, bh2, bh3, bl0, bl1, bl2, bl3;
                LDSM4(bh0, bh1, bh2, bh3, base + T_BH + (bBase[g] ^ kb));
                LDSM4(bl0, bl1, bl2, bl3, base + T_BL + (bBase[g] ^ kb));
#pragma unroll
                for (int mt = 0; mt < 4; mt++) {
                    // P1: Ah*Bh
                    MMA(acc[mt][2*g+0], ah[mt][0], ah[mt][1], ah[mt][2], ah[mt][3], bh0, bh2);
                    MMA(acc[mt][2*g+1], ah[mt][0], ah[mt][1], ah[mt][2], ah[mt][3], bh1, bh3);
                    // P2: Ah*Bl
                    MMA(acc[mt][2*g+0], ah[mt][0], ah[mt][1], ah[mt][2], ah[mt][3], bl0, bl2);
                    MMA(acc[mt][2*g+1], ah[mt][0], ah[mt][1], ah[mt][2], ah[mt][3], bl1, bl3);
                    // P3: Al*Bh
                    MMA(acc[mt][2*g+0], al[mt][0], al[mt][1], al[mt][2], al[mt][3], bh0, bh2);
                    MMA(acc[mt][2*g+1], al[mt][0], al[mt][1], al[mt][2], al[mt][3], bh1, bh3);
                }
            }
        }

        __syncthreads();                       // all warps done with buf (s&1)
        if (s + 2 < NSTAGE) load_stage(s + 2, s & 1);
    }

    // ---- epilogue: bias + scatter straight from C fragments ----
    // C frag: c0,c1 -> (row lane>>2, col 2*(lane&3)+{0,1}); c2,c3 -> row+8.
    const int trow = lane >> 2;
    const int tcol = (lane & 3) * 2;
    int   oc0[8], oc1[8];
    float bv0[8], bv1[8];
#pragma unroll
    for (int nt = 0; nt < 8; nt++) {
        const int n = n0 + warp_n * 64 + nt * 8 + tcol;
        oc0[nt] = __ldg(&out_idx[n]);     oc1[nt] = __ldg(&out_idx[n + 1]);
        bv0[nt] = __ldg(&bias[n]);        bv1[nt] = __ldg(&bias[n + 1]);
    }
#pragma unroll
    for (int mt = 0; mt < 4; mt++) {
        const int m = m0 + warp_m * 64 + mt * 16 + trow;
        float* r0 = out + (size_t)m * OUT_F;
        float* r1 = out + (size_t)(m + 8) * OUT_F;
#pragma unroll
        for (int nt = 0; nt < 8; nt++) {
            r0[oc0[nt]] = acc[mt][nt][0] + bv0[nt];
            r0[oc1[nt]] = acc[mt][nt][1] + bv1[nt];
            r1[oc0[nt]] = acc[mt][nt][2] + bv0[nt];
            r1[oc1[nt]] = acc[mt][nt][3] + bv1[nt];
        }
    }
}

// ---------------------------------------------------------------------------
// Launch
// ---------------------------------------------------------------------------
extern "C" void kernel_launch(void* const* d_in, const int* in_sizes, int n_in,
                              void* d_out, int out_size) {
    const float* x       = (const float*)d_in[0];
    const float* weight  = (const float*)d_in[1];
    const float* bias    = (const float*)d_in[2];
    const int*   in_idx  = (const int*)d_in[3];
    const int*   out_idx = (const int*)d_in[4];
    float* out = (float*)d_out;

    // zero full output (inactive columns must be 0; buffer is poisoned)
    cudaMemsetAsync(out, 0, (size_t)out_size * sizeof(float), 0);

    // pre-pass: gather + bf16 split
    {
        dim3 g(ACT_IN / 256, NROWS);
        nsl_split_x<<<g, 256>>>(x, in_idx);
    }
    nsl_split_w<<<(ACT_OUT * ACT_IN) / 256, 256>>>(weight);

    // tensor-core GEMM (mma.sync) + bias + scatter
    cudaFuncSetAttribute(nsl_mma, cudaFuncAttributeMaxDynamicSharedMemorySize,
                         SMEM_TOTAL);
    dim3 grid(ACT_OUT / BN, NROWS / BM);   // 64 x 32
    nsl_mma<<<grid, NTH, SMEM_TOTAL>>>(bias, out_idx, out);
}

// round 8
// speedup vs baseline: 1.4211x; 1.4211x over previous
#include <cuda_runtime.h>
#include <cuda_fp16.h>
#include <cstdint>

// ---------------------------------------------------------------------------
// Problem constants
// ---------------------------------------------------------------------------
#define IN_F    4096
#define OUT_F   16384
#define ACT_IN  2048
#define ACT_OUT 8192
#define NROWS   8192      // B*S

// GEMM tiling: CTA 256(M) x 128(N), 8 warps as 4(M) x 2(N), warp tile 64x64
#define BM 256
#define BN 128
#define KC 64                    // K elements per stage (128 B/row in smem)
#define NSTAGE (ACT_IN / KC)     // 32
#define NTH 256

// SMEM per stage: Ah 32K | Al 32K | B 16K = 80 KB; 2 stages = 160 KB
#define T_AH 0
#define T_AL 32768
#define T_B  65536
#define STAGE_BYTES 81920
#define SMEM_TOTAL  163840

// fp16-split operand scratch (allocation-free rule: __device__ globals)
// A split exactly into hi+lo fp16; B rounded once to fp16 (error ~2^-12/elem,
// norm rel err ~2e-4 over K=2048 — 5x under the 1e-3 gate).
__device__ __half g_Ah[(size_t)NROWS * ACT_IN];
__device__ __half g_Al[(size_t)NROWS * ACT_IN];
__device__ __half g_B [(size_t)ACT_OUT * ACT_IN];

// ---------------------------------------------------------------------------
// PTX helpers (sm_80-baseline only — harness lowers through plain compute_103)
// ---------------------------------------------------------------------------
__device__ __forceinline__ uint32_t smem_u32(const void* p) {
    uint32_t a;
    asm("{ .reg .u64 t; cvta.to.shared.u64 t, %1; cvt.u32.u64 %0, t; }"
        : "=r"(a) : "l"(p));
    return a;
}

#define SWZ(o) ((o) ^ (((o) >> 3) & 0x70))   // SW128 xor swizzle (16B granules)

#define CPA16(sa, gp) \
    asm volatile("cp.async.cg.shared.global [%0], [%1], 16;" :: "r"(sa), "l"(gp) : "memory")
#define CPA_COMMIT() asm volatile("cp.async.commit_group;" ::: "memory")
#define CPA_WAIT(n)  asm volatile("cp.async.wait_group %0;" :: "n"(n) : "memory")

#define LDSM4(r0, r1, r2, r3, a) \
    asm volatile("ldmatrix.sync.aligned.m8n8.x4.shared.b16 {%0,%1,%2,%3}, [%4];" \
                 : "=r"(r0), "=r"(r1), "=r"(r2), "=r"(r3) : "r"(a))

// D += A*B, fp16 in, fp32 accum.  A frag 4xb32, B frag 2xb32, C 4xf32.
#define MMA(c, a0, a1, a2, a3, b0, b1) \
    asm volatile("mma.sync.aligned.m16n8k16.row.col.f32.f16.f16.f32 " \
                 "{%0,%1,%2,%3}, {%4,%5,%6,%7}, {%8,%9}, {%0,%1,%2,%3};" \
                 : "+f"((c)[0]), "+f"((c)[1]), "+f"((c)[2]), "+f"((c)[3]) \
                 : "r"(a0), "r"(a1), "r"(a2), "r"(a3), "r"(b0), "r"(b1))

// ---------------------------------------------------------------------------
// Pre-pass 1: gather active input cols + split fp32 -> fp16 hi/lo (exact)
// ---------------------------------------------------------------------------
__global__ void nsl_split_x(const float* __restrict__ x,
                            const int* __restrict__ in_idx) {
    const int k = blockIdx.x * blockDim.x + threadIdx.x;
    const int m = blockIdx.y;
    const int c = __ldg(&in_idx[k]);
    const float v = __ldg(&x[(size_t)m * IN_F + c]);
    const __half h = __float2half_rn(v);
    const __half l = __float2half_rn(v - __half2float(h));
    g_Ah[(size_t)m * ACT_IN + k] = h;
    g_Al[(size_t)m * ACT_IN + k] = l;
}

// Pre-pass 2: round weight fp32 -> fp16 (single)
__global__ void nsl_round_w(const float* __restrict__ w) {
    const size_t i = blockIdx.x * (size_t)blockDim.x + threadIdx.x;
    g_B[i] = __float2half_rn(__ldg(&w[i]));
}

// ---------------------------------------------------------------------------
// Main GEMM: C[m, out_idx[n]] = sum_k (Ah+Al)[m,k]*B[n,k] + bias[n]
// 2 HMMA products (AhB + AlB), fp32 register accumulation.
// ---------------------------------------------------------------------------
__global__ __launch_bounds__(NTH, 1)
void nsl_mma(const float* __restrict__ bias,
             const int*   __restrict__ out_idx,
             float*       __restrict__ out) {
    extern __shared__ __align__(1024) char smem[];
    const uint32_t sb = smem_u32(smem);
    const int tid  = threadIdx.x;
    const int wid  = tid >> 5;
    const int lane = tid & 31;
    const int m0 = blockIdx.y * BM;
    const int n0 = blockIdx.x * BN;

    const int warp_m = wid >> 1;       // 0..3  -> 64-row slab of M
    const int warp_n = wid & 1;        // 0..1  -> 64-col slab of N

    // ---- cp.async slot mapping ----
    // A tiles: 256 rows x 8 x 16B = 2048 chunks -> 8/thread (each of Ah, Al)
    // B tile : 128 rows x 8 x 16B = 1024 chunks -> 4/thread
    int aG[8]; uint32_t aS[8];
    int bG[4]; uint32_t bS[4];
#pragma unroll
    for (int i = 0; i < 8; i++) {
        const int id = tid + i * NTH;
        const int r = id >> 3, cv = id & 7;
        aG[i] = r * ACT_IN + cv * 8;
        aS[i] = SWZ((uint32_t)(r * 128 + cv * 16));
    }
#pragma unroll
    for (int i = 0; i < 4; i++) {
        const int id = tid + i * NTH;
        const int r = id >> 3, cv = id & 7;
        bG[i] = r * ACT_IN + cv * 8;
        bS[i] = SWZ((uint32_t)(r * 128 + cv * 16));
    }
    const __half* pAh = g_Ah + (size_t)m0 * ACT_IN;
    const __half* pAl = g_Al + (size_t)m0 * ACT_IN;
    const __half* pB  = g_B  + (size_t)n0 * ACT_IN;

    auto load_stage = [&](int s, int b) {
        const uint32_t base = sb + b * STAGE_BYTES;
        const int ke = s * KC;
#pragma unroll
        for (int i = 0; i < 8; i++) {
            CPA16(base + T_AH + aS[i], pAh + ke + aG[i]);
            CPA16(base + T_AL + aS[i], pAl + ke + aG[i]);
        }
#pragma unroll
        for (int i = 0; i < 4; i++)
            CPA16(base + T_B + bS[i], pB + ke + bG[i]);
        CPA_COMMIT();
    };

    // ---- ldmatrix lane addressing ----
    // SWZ(row*128 + kb) = row*128 + (((row&7)<<4) ^ kb) for kb < 128.
    const int lrow  = lane & 15;
    const uint32_t lkoff = (uint32_t)((lane >> 4) * 16);

    uint32_t aBase[4];
#pragma unroll
    for (int mt = 0; mt < 4; mt++) {
        const int row = warp_m * 64 + mt * 16 + lrow;
        aBase[mt] = (uint32_t)(row * 128) + (((uint32_t)(row & 7)) << 4);
    }
    uint32_t bBase[4];
#pragma unroll
    for (int g = 0; g < 4; g++) {
        const int row = warp_n * 64 + g * 16 + lrow;
        bBase[g] = (uint32_t)(row * 128) + (((uint32_t)(row & 7)) << 4);
    }

    // ---- accumulators: 4 m-tiles x 8 n8-tiles x 4 f32 = 128 regs ----
    float acc[4][8][4];
#pragma unroll
    for (int i = 0; i < 4; i++)
#pragma unroll
        for (int j = 0; j < 8; j++)
#pragma unroll
            for (int q = 0; q < 4; q++) acc[i][j][q] = 0.0f;

    // ---- pipeline prologue ----
    load_stage(0, 0);
    load_stage(1, 1);

    for (int s = 0; s < NSTAGE; s++) {
        if (s < NSTAGE - 1) { CPA_WAIT(1); } else { CPA_WAIT(0); }
        __syncthreads();

        const uint32_t base = sb + (s & 1) * STAGE_BYTES;

#pragma unroll
        for (int ks = 0; ks < 4; ks++) {
            const uint32_t kb = (uint32_t)(ks * 32) + lkoff;

            // A fragments (hi and lo) for this k16: 4 m-tiles each (32 regs)
            uint32_t ah[4][4], al[4][4];
#pragma unroll
            for (int mt = 0; mt < 4; mt++)
                LDSM4(ah[mt][0], ah[mt][1], ah[mt][2], ah[mt][3],
                      base + T_AH + (aBase[mt] ^ kb));
#pragma unroll
            for (int mt = 0; mt < 4; mt++)
                LDSM4(al[mt][0], al[mt][1], al[mt][2], al[mt][3],
                      base + T_AL + (aBase[mt] ^ kb));

            // Stream B in 4 groups of n16 (4 transient regs each)
#pragma unroll
            for (int g = 0; g < 4; g++) {
                uint32_t b0, b1, b2, b3;
                LDSM4(b0, b1, b2, b3, base + T_B + (bBase[g] ^ kb));
#pragma unroll
                for (int mt = 0; mt < 4; mt++) {
                    MMA(acc[mt][2*g+0], ah[mt][0], ah[mt][1], ah[mt][2], ah[mt][3], b0, b2);
                    MMA(acc[mt][2*g+1], ah[mt][0], ah[mt][1], ah[mt][2], ah[mt][3], b1, b3);
                    MMA(acc[mt][2*g+0], al[mt][0], al[mt][1], al[mt][2], al[mt][3], b0, b2);
                    MMA(acc[mt][2*g+1], al[mt][0], al[mt][1], al[mt][2], al[mt][3], b1, b3);
                }
            }
        }

        __syncthreads();                       // all warps done with buf (s&1)
        if (s + 2 < NSTAGE) load_stage(s + 2, s & 1);
    }

    // ---- epilogue: bias + scatter straight from C fragments ----
    const int trow = lane >> 2;
    const int tcol = (lane & 3) * 2;
    int   oc0[8], oc1[8];
    float bv0[8], bv1[8];
#pragma unroll
    for (int nt = 0; nt < 8; nt++) {
        const int n = n0 + warp_n * 64 + nt * 8 + tcol;
        oc0[nt] = __ldg(&out_idx[n]);     oc1[nt] = __ldg(&out_idx[n + 1]);
        bv0[nt] = __ldg(&bias[n]);        bv1[nt] = __ldg(&bias[n + 1]);
    }
#pragma unroll
    for (int mt = 0; mt < 4; mt++) {
        const int m = m0 + warp_m * 64 + mt * 16 + trow;
        float* r0 = out + (size_t)m * OUT_F;
        float* r1 = out + (size_t)(m + 8) * OUT_F;
#pragma unroll
        for (int nt = 0; nt < 8; nt++) {
            r0[oc0[nt]] = acc[mt][nt][0] + bv0[nt];
            r0[oc1[nt]] = acc[mt][nt][1] + bv1[nt];
            r1[oc0[nt]] = acc[mt][nt][2] + bv0[nt];
            r1[oc1[nt]] = acc[mt][nt][3] + bv1[nt];
        }
    }
}

// ---------------------------------------------------------------------------
// Launch
// ---------------------------------------------------------------------------
extern "C" void kernel_launch(void* const* d_in, const int* in_sizes, int n_in,
                              void* d_out, int out_size) {
    const float* x       = (const float*)d_in[0];
    const float* weight  = (const float*)d_in[1];
    const float* bias    = (const float*)d_in[2];
    const int*   in_idx  = (const int*)d_in[3];
    const int*   out_idx = (const int*)d_in[4];
    float* out = (float*)d_out;

    // zero full output (inactive columns must be 0; buffer is poisoned)
    cudaMemsetAsync(out, 0, (size_t)out_size * sizeof(float), 0);

    // pre-pass: gather + fp16 split (A) / round (B)
    {
        dim3 g(ACT_IN / 256, NROWS);
        nsl_split_x<<<g, 256>>>(x, in_idx);
    }
    nsl_round_w<<<(ACT_OUT * ACT_IN) / 256, 256>>>(weight);

    // tensor-core GEMM (mma.sync) + bias + scatter
    cudaFuncSetAttribute(nsl_mma, cudaFuncAttributeMaxDynamicSharedMemorySize,
                         SMEM_TOTAL);
    dim3 grid(ACT_OUT / BN, NROWS / BM);   // 64 x 32
    nsl_mma<<<grid, NTH, SMEM_TOTAL>>>(bias, out_idx, out);
}

// round 9
// speedup vs baseline: 2.1651x; 1.5235x over previous
#include <cuda_runtime.h>
#include <cuda_fp16.h>
#include <cstdint>

// ---------------------------------------------------------------------------
// Problem constants
// ---------------------------------------------------------------------------
#define IN_F    4096
#define OUT_F   16384
#define ACT_IN  2048
#define ACT_OUT 8192
#define NROWS   8192      // B*S

// GEMM tiling: CTA 256(M) x 128(N), 8 warps as 4(M) x 2(N), warp tile 64x64
#define BM 256
#define BN 128
#define KC 64                    // K elements per stage (128 B/row in smem)
#define NSTAGE (ACT_IN / KC)     // 32
#define NTH 256

// SMEM per stage: A 32K | B 16K = 48 KB; 2 stages = 96 KB
#define T_A 0
#define T_B 32768
#define STAGE_BYTES 49152
#define SMEM_TOTAL  98304

// fp16 operand scratch (allocation-free rule: __device__ globals).
// Both operands rounded once to fp16: independent rounding errors,
// measured single-side err 2.07e-4 @K=2048 -> combined ~2.9e-4 << 1e-3 gate.
__device__ __half g_A[(size_t)NROWS * ACT_IN];
__device__ __half g_B[(size_t)ACT_OUT * ACT_IN];

// ---------------------------------------------------------------------------
// PTX helpers (sm_80-baseline only — harness lowers through plain compute_103)
// ---------------------------------------------------------------------------
__device__ __forceinline__ uint32_t smem_u32(const void* p) {
    uint32_t a;
    asm("{ .reg .u64 t; cvta.to.shared.u64 t, %1; cvt.u32.u64 %0, t; }"
        : "=r"(a) : "l"(p));
    return a;
}

#define SWZ(o) ((o) ^ (((o) >> 3) & 0x70))   // SW128 xor swizzle (16B granules)

#define CPA16(sa, gp) \
    asm volatile("cp.async.cg.shared.global [%0], [%1], 16;" :: "r"(sa), "l"(gp) : "memory")
#define CPA_COMMIT() asm volatile("cp.async.commit_group;" ::: "memory")
#define CPA_WAIT(n)  asm volatile("cp.async.wait_group %0;" :: "n"(n) : "memory")

#define LDSM4(r0, r1, r2, r3, a) \
    asm volatile("ldmatrix.sync.aligned.m8n8.x4.shared.b16 {%0,%1,%2,%3}, [%4];" \
                 : "=r"(r0), "=r"(r1), "=r"(r2), "=r"(r3) : "r"(a))

// D += A*B, fp16 in, fp32 accum.  A frag 4xb32, B frag 2xb32, C 4xf32.
#define MMA(c, a0, a1, a2, a3, b0, b1) \
    asm volatile("mma.sync.aligned.m16n8k16.row.col.f32.f16.f16.f32 " \
                 "{%0,%1,%2,%3}, {%4,%5,%6,%7}, {%8,%9}, {%0,%1,%2,%3};" \
                 : "+f"((c)[0]), "+f"((c)[1]), "+f"((c)[2]), "+f"((c)[3]) \
                 : "r"(a0), "r"(a1), "r"(a2), "r"(a3), "r"(b0), "r"(b1))

// ---------------------------------------------------------------------------
// Pre-pass 1: gather active input cols, round fp32 -> fp16
// ---------------------------------------------------------------------------
__global__ void nsl_gather_x(const float* __restrict__ x,
                             const int* __restrict__ in_idx) {
    const int k = blockIdx.x * blockDim.x + threadIdx.x;
    const int m = blockIdx.y;
    const int c = __ldg(&in_idx[k]);
    g_A[(size_t)m * ACT_IN + k] = __float2half_rn(__ldg(&x[(size_t)m * IN_F + c]));
}

// Pre-pass 2: round weight fp32 -> fp16
__global__ void nsl_round_w(const float* __restrict__ w) {
    const size_t i = blockIdx.x * (size_t)blockDim.x + threadIdx.x;
    g_B[i] = __float2half_rn(__ldg(&w[i]));
}

// ---------------------------------------------------------------------------
// Main GEMM: C[m, out_idx[n]] = sum_k A[m,k]*B[n,k] + bias[n]
// Single fp16 HMMA product, fp32 register accumulation.
// ---------------------------------------------------------------------------
__global__ __launch_bounds__(NTH, 1)
void nsl_mma(const float* __restrict__ bias,
             const int*   __restrict__ out_idx,
             float*       __restrict__ out) {
    extern __shared__ __align__(1024) char smem[];
    const uint32_t sb = smem_u32(smem);
    const int tid  = threadIdx.x;
    const int wid  = tid >> 5;
    const int lane = tid & 31;
    const int m0 = blockIdx.y * BM;
    const int n0 = blockIdx.x * BN;

    const int warp_m = wid >> 1;       // 0..3  -> 64-row slab of M
    const int warp_n = wid & 1;        // 0..1  -> 64-col slab of N

    // ---- cp.async slot mapping ----
    // A tile: 256 rows x 8 x 16B = 2048 chunks -> 8/thread
    // B tile: 128 rows x 8 x 16B = 1024 chunks -> 4/thread
    int aG[8]; uint32_t aS[8];
    int bG[4]; uint32_t bS[4];
#pragma unroll
    for (int i = 0; i < 8; i++) {
        const int id = tid + i * NTH;
        const int r = id >> 3, cv = id & 7;
        aG[i] = r * ACT_IN + cv * 8;
        aS[i] = SWZ((uint32_t)(r * 128 + cv * 16));
    }
#pragma unroll
    for (int i = 0; i < 4; i++) {
        const int id = tid + i * NTH;
        const int r = id >> 3, cv = id & 7;
        bG[i] = r * ACT_IN + cv * 8;
        bS[i] = SWZ((uint32_t)(r * 128 + cv * 16));
    }
    const __half* pA = g_A + (size_t)m0 * ACT_IN;
    const __half* pB = g_B + (size_t)n0 * ACT_IN;

    auto load_stage = [&](int s, int b) {
        const uint32_t base = sb + b * STAGE_BYTES;
        const int ke = s * KC;
#pragma unroll
        for (int i = 0; i < 8; i++)
            CPA16(base + T_A + aS[i], pA + ke + aG[i]);
#pragma unroll
        for (int i = 0; i < 4; i++)
            CPA16(base + T_B + bS[i], pB + ke + bG[i]);
        CPA_COMMIT();
    };

    // ---- ldmatrix lane addressing ----
    // SWZ(row*128 + kb) = row*128 + (((row&7)<<4) ^ kb) for kb < 128.
    const int lrow  = lane & 15;
    const uint32_t lkoff = (uint32_t)((lane >> 4) * 16);

    uint32_t aBase[4];
#pragma unroll
    for (int mt = 0; mt < 4; mt++) {
        const int row = warp_m * 64 + mt * 16 + lrow;
        aBase[mt] = (uint32_t)(row * 128) + (((uint32_t)(row & 7)) << 4);
    }
    uint32_t bBase[4];
#pragma unroll
    for (int g = 0; g < 4; g++) {
        const int row = warp_n * 64 + g * 16 + lrow;
        bBase[g] = (uint32_t)(row * 128) + (((uint32_t)(row & 7)) << 4);
    }

    // ---- accumulators: 4 m-tiles x 8 n8-tiles x 4 f32 = 128 regs ----
    float acc[4][8][4];
#pragma unroll
    for (int i = 0; i < 4; i++)
#pragma unroll
        for (int j = 0; j < 8; j++)
#pragma unroll
            for (int q = 0; q < 4; q++) acc[i][j][q] = 0.0f;

    // ---- pipeline prologue ----
    load_stage(0, 0);
    load_stage(1, 1);

    for (int s = 0; s < NSTAGE; s++) {
        if (s < NSTAGE - 1) { CPA_WAIT(1); } else { CPA_WAIT(0); }
        __syncthreads();

        const uint32_t base = sb + (s & 1) * STAGE_BYTES;

#pragma unroll
        for (int ks = 0; ks < 4; ks++) {
            const uint32_t kb = (uint32_t)(ks * 32) + lkoff;

            // A fragments for this k16: 4 m-tiles (16 regs)
            uint32_t ah[4][4];
#pragma unroll
            for (int mt = 0; mt < 4; mt++)
                LDSM4(ah[mt][0], ah[mt][1], ah[mt][2], ah[mt][3],
                      base + T_A + (aBase[mt] ^ kb));

            // Stream B in 4 groups of n16 (4 transient regs each)
#pragma unroll
            for (int g = 0; g < 4; g++) {
                uint32_t b0, b1, b2, b3;
                LDSM4(b0, b1, b2, b3, base + T_B + (bBase[g] ^ kb));
#pragma unroll
                for (int mt = 0; mt < 4; mt++) {
                    MMA(acc[mt][2*g+0], ah[mt][0], ah[mt][1], ah[mt][2], ah[mt][3], b0, b2);
                    MMA(acc[mt][2*g+1], ah[mt][0], ah[mt][1], ah[mt][2], ah[mt][3], b1, b3);
                }
            }
        }

        __syncthreads();                       // all warps done with buf (s&1)
        if (s + 2 < NSTAGE) load_stage(s + 2, s & 1);
    }

    // ---- epilogue: bias + scatter straight from C fragments ----
    const int trow = lane >> 2;
    const int tcol = (lane & 3) * 2;
    int   oc0[8], oc1[8];
    float bv0[8], bv1[8];
#pragma unroll
    for (int nt = 0; nt < 8; nt++) {
        const int n = n0 + warp_n * 64 + nt * 8 + tcol;
        oc0[nt] = __ldg(&out_idx[n]);     oc1[nt] = __ldg(&out_idx[n + 1]);
        bv0[nt] = __ldg(&bias[n]);        bv1[nt] = __ldg(&bias[n + 1]);
    }
#pragma unroll
    for (int mt = 0; mt < 4; mt++) {
        const int m = m0 + warp_m * 64 + mt * 16 + trow;
        float* r0 = out + (size_t)m * OUT_F;
        float* r1 = out + (size_t)(m + 8) * OUT_F;
#pragma unroll
        for (int nt = 0; nt < 8; nt++) {
            r0[oc0[nt]] = acc[mt][nt][0] + bv0[nt];
            r0[oc1[nt]] = acc[mt][nt][1] + bv1[nt];
            r1[oc0[nt]] = acc[mt][nt][2] + bv0[nt];
            r1[oc1[nt]] = acc[mt][nt][3] + bv1[nt];
        }
    }
}

// ---------------------------------------------------------------------------
// Launch
// ---------------------------------------------------------------------------
extern "C" void kernel_launch(void* const* d_in, const int* in_sizes, int n_in,
                              void* d_out, int out_size) {
    const float* x       = (const float*)d_in[0];
    const float* weight  = (const float*)d_in[1];
    const float* bias    = (const float*)d_in[2];
    const int*   in_idx  = (const int*)d_in[3];
    const int*   out_idx = (const int*)d_in[4];
    float* out = (float*)d_out;

    // zero full output (inactive columns must be 0; buffer is poisoned)
    cudaMemsetAsync(out, 0, (size_t)out_size * sizeof(float), 0);

    // pre-pass: gather + fp16 round
    {
        dim3 g(ACT_IN / 256, NROWS);
        nsl_gather_x<<<g, 256>>>(x, in_idx);
    }
    nsl_round_w<<<(ACT_OUT * ACT_IN) / 256, 256>>>(weight);

    // tensor-core GEMM (mma.sync) + bias + scatter
    cudaFuncSetAttribute(nsl_mma, cudaFuncAttributeMaxDynamicSharedMemorySize,
                         SMEM_TOTAL);
    dim3 grid(ACT_OUT / BN, NROWS / BM);   // 64 x 32
    nsl_mma<<<grid, NTH, SMEM_TOTAL>>>(bias, out_idx, out);
}

// round 10
// speedup vs baseline: 2.2948x; 1.0599x over previous
#include <cuda_runtime.h>
#include <cuda_fp16.h>
#include <cstdint>

// ---------------------------------------------------------------------------
// Problem constants
// ---------------------------------------------------------------------------
#define IN_F    4096
#define OUT_F   16384
#define ACT_IN  2048
#define ACT_OUT 8192
#define NROWS   8192      // B*S

// GEMM tiling: CTA 256(M) x 128(N), 8 warps as 4(M) x 2(N), warp tile 64x64
#define BM 256
#define BN 128
#define KC 64                    // K elements per stage (128 B/row in smem)
#define NSTAGE (ACT_IN / KC)     // 32
#define NTH 256
#define NBUF 4                   // cp.async pipeline depth

// SMEM per stage: A 32K | B 16K = 48 KB; 4 stages = 192 KB
#define T_A 0
#define T_B 32768
#define STAGE_BYTES 49152
#define SMEM_TOTAL  (NBUF * STAGE_BYTES)   // 196608

// fp16 operand scratch (allocation-free rule: __device__ globals).
// Both operands rounded once to fp16; measured: one rounded side -> 2.07e-4,
// both sides -> 2.93e-4 (= sqrt(2)x), comfortably under the 1e-3 gate.
__device__ __half g_A[(size_t)NROWS * ACT_IN];
__device__ __half g_B[(size_t)ACT_OUT * ACT_IN];

// ---------------------------------------------------------------------------
// PTX helpers (sm_80-baseline only — harness lowers through plain compute_103)
// ---------------------------------------------------------------------------
__device__ __forceinline__ uint32_t smem_u32(const void* p) {
    uint32_t a;
    asm("{ .reg .u64 t; cvta.to.shared.u64 t, %1; cvt.u32.u64 %0, t; }"
        : "=r"(a) : "l"(p));
    return a;
}

#define SWZ(o) ((o) ^ (((o) >> 3) & 0x70))   // SW128 xor swizzle (16B granules)

#define CPA16(sa, gp) \
    asm volatile("cp.async.cg.shared.global [%0], [%1], 16;" :: "r"(sa), "l"(gp) : "memory")
#define CPA_COMMIT() asm volatile("cp.async.commit_group;" ::: "memory")
#define CPA_WAIT(n)  asm volatile("cp.async.wait_group %0;" :: "n"(n) : "memory")

#define LDSM4(r0, r1, r2, r3, a) \
    asm volatile("ldmatrix.sync.aligned.m8n8.x4.shared.b16 {%0,%1,%2,%3}, [%4];" \
                 : "=r"(r0), "=r"(r1), "=r"(r2), "=r"(r3) : "r"(a))

// D += A*B, fp16 in, fp32 accum.  A frag 4xb32, B frag 2xb32, C 4xf32.
#define MMA(c, a0, a1, a2, a3, b0, b1) \
    asm volatile("mma.sync.aligned.m16n8k16.row.col.f32.f16.f16.f32 " \
                 "{%0,%1,%2,%3}, {%4,%5,%6,%7}, {%8,%9}, {%0,%1,%2,%3};" \
                 : "+f"((c)[0]), "+f"((c)[1]), "+f"((c)[2]), "+f"((c)[3]) \
                 : "r"(a0), "r"(a1), "r"(a2), "r"(a3), "r"(b0), "r"(b1))

// ---------------------------------------------------------------------------
// Pre-pass 1: gather active cols -> fp16, AND zero the output buffer
// (fused: each of the 16M threads also writes 32 B of zeros, coalesced).
// ---------------------------------------------------------------------------
__global__ void nsl_gather_x(const float* __restrict__ x,
                             const int* __restrict__ in_idx,
                             float4* __restrict__ outv) {
    const int k = blockIdx.x * blockDim.x + threadIdx.x;
    const int m = blockIdx.y;
    const int c = __ldg(&in_idx[k]);
    g_A[(size_t)m * ACT_IN + k] = __float2half_rn(__ldg(&x[(size_t)m * IN_F + c]));

    // zero 8 floats (2 float4) of out: total 16M threads * 32B = 512 MB exactly
    const size_t gid = ((size_t)blockIdx.y * gridDim.x + blockIdx.x) * blockDim.x
                       + threadIdx.x;
    const float4 z = {0.f, 0.f, 0.f, 0.f};
    outv[gid * 2 + 0] = z;
    outv[gid * 2 + 1] = z;
}

// Pre-pass 2: round weight fp32 -> fp16
__global__ void nsl_round_w(const float* __restrict__ w) {
    const size_t i = blockIdx.x * (size_t)blockDim.x + threadIdx.x;
    g_B[i] = __float2half_rn(__ldg(&w[i]));
}

// ---------------------------------------------------------------------------
// Main GEMM: C[m, out_idx[n]] = sum_k A[m,k]*B[n,k] + bias[n]
// Single fp16 HMMA product, fp32 register accumulation, 4-stage pipeline.
// ---------------------------------------------------------------------------
__global__ __launch_bounds__(NTH, 1)
void nsl_mma(const float* __restrict__ bias,
             const int*   __restrict__ out_idx,
             float*       __restrict__ out) {
    extern __shared__ __align__(1024) char smem[];
    const uint32_t sb = smem_u32(smem);
    const int tid  = threadIdx.x;
    const int wid  = tid >> 5;
    const int lane = tid & 31;
    const int m0 = blockIdx.y * BM;
    const int n0 = blockIdx.x * BN;

    const int warp_m = wid >> 1;       // 0..3  -> 64-row slab of M
    const int warp_n = wid & 1;        // 0..1  -> 64-col slab of N

    // ---- cp.async slot mapping ----
    int aG[8]; uint32_t aS[8];
    int bG[4]; uint32_t bS[4];
#pragma unroll
    for (int i = 0; i < 8; i++) {
        const int id = tid + i * NTH;
        const int r = id >> 3, cv = id & 7;
        aG[i] = r * ACT_IN + cv * 8;
        aS[i] = SWZ((uint32_t)(r * 128 + cv * 16));
    }
#pragma unroll
    for (int i = 0; i < 4; i++) {
        const int id = tid + i * NTH;
        const int r = id >> 3, cv = id & 7;
        bG[i] = r * ACT_IN + cv * 8;
        bS[i] = SWZ((uint32_t)(r * 128 + cv * 16));
    }
    const __half* pA = g_A + (size_t)m0 * ACT_IN;
    const __half* pB = g_B + (size_t)n0 * ACT_IN;

    auto load_stage = [&](int s) {
        const uint32_t base = sb + (s & (NBUF - 1)) * STAGE_BYTES;
        const int ke = s * KC;
#pragma unroll
        for (int i = 0; i < 8; i++)
            CPA16(base + T_A + aS[i], pA + ke + aG[i]);
#pragma unroll
        for (int i = 0; i < 4; i++)
            CPA16(base + T_B + bS[i], pB + ke + bG[i]);
        CPA_COMMIT();
    };

    // ---- ldmatrix lane addressing ----
    // SWZ(row*128 + kb) = row*128 + (((row&7)<<4) ^ kb) for kb < 128.
    const int lrow  = lane & 15;
    const uint32_t lkoff = (uint32_t)((lane >> 4) * 16);

    uint32_t aBase[4];
#pragma unroll
    for (int mt = 0; mt < 4; mt++) {
        const int row = warp_m * 64 + mt * 16 + lrow;
        aBase[mt] = (uint32_t)(row * 128) + (((uint32_t)(row & 7)) << 4);
    }
    uint32_t bBase[4];
#pragma unroll
    for (int g = 0; g < 4; g++) {
        const int row = warp_n * 64 + g * 16 + lrow;
        bBase[g] = (uint32_t)(row * 128) + (((uint32_t)(row & 7)) << 4);
    }

    // ---- accumulators: 4 m-tiles x 8 n8-tiles x 4 f32 = 128 regs ----
    float acc[4][8][4];
#pragma unroll
    for (int i = 0; i < 4; i++)
#pragma unroll
        for (int j = 0; j < 8; j++)
#pragma unroll
            for (int q = 0; q < 4; q++) acc[i][j][q] = 0.0f;

    // ---- prologue: 3 stages in flight ----
    load_stage(0);
    load_stage(1);
    load_stage(2);

    for (int s = 0; s < NSTAGE; s++) {
        CPA_WAIT(2);          // pending {s, s+1, s+2} -> group s complete
        __syncthreads();      // fences compute s-1 (last reader of buf (s+3)%4)

        if (s + 3 < NSTAGE) load_stage(s + 3);   // refills buf (s-1)%4

        const uint32_t base = sb + (s & (NBUF - 1)) * STAGE_BYTES;

#pragma unroll
        for (int ks = 0; ks < 4; ks++) {
            const uint32_t kb = (uint32_t)(ks * 32) + lkoff;

            // A fragments for this k16: 4 m-tiles (16 regs)
            uint32_t ah[4][4];
#pragma unroll
            for (int mt = 0; mt < 4; mt++)
                LDSM4(ah[mt][0], ah[mt][1], ah[mt][2], ah[mt][3],
                      base + T_A + (aBase[mt] ^ kb));

            // Stream B in 4 groups of n16 (4 transient regs each)
#pragma unroll
            for (int g = 0; g < 4; g++) {
                uint32_t b0, b1, b2, b3;
                LDSM4(b0, b1, b2, b3, base + T_B + (bBase[g] ^ kb));
#pragma unroll
                for (int mt = 0; mt < 4; mt++) {
                    MMA(acc[mt][2*g+0], ah[mt][0], ah[mt][1], ah[mt][2], ah[mt][3], b0, b2);
                    MMA(acc[mt][2*g+1], ah[mt][0], ah[mt][1], ah[mt][2], ah[mt][3], b1, b3);
                }
            }
        }
    }

    // ---- epilogue: bias + scatter straight from C fragments ----
    const int trow = lane >> 2;
    const int tcol = (lane & 3) * 2;
    int   oc0[8], oc1[8];
    float bv0[8], bv1[8];
#pragma unroll
    for (int nt = 0; nt < 8; nt++) {
        const int n = n0 + warp_n * 64 + nt * 8 + tcol;
        oc0[nt] = __ldg(&out_idx[n]);     oc1[nt] = __ldg(&out_idx[n + 1]);
        bv0[nt] = __ldg(&bias[n]);        bv1[nt] = __ldg(&bias[n + 1]);
    }
#pragma unroll
    for (int mt = 0; mt < 4; mt++) {
        const int m = m0 + warp_m * 64 + mt * 16 + trow;
        float* r0 = out + (size_t)m * OUT_F;
        float* r1 = out + (size_t)(m + 8) * OUT_F;
#pragma unroll
        for (int nt = 0; nt < 8; nt++) {
            r0[oc0[nt]] = acc[mt][nt][0] + bv0[nt];
            r0[oc1[nt]] = acc[mt][nt][1] + bv1[nt];
            r1[oc0[nt]] = acc[mt][nt][2] + bv0[nt];
            r1[oc1[nt]] = acc[mt][nt][3] + bv1[nt];
        }
    }
}

// ---------------------------------------------------------------------------
// Launch
// ---------------------------------------------------------------------------
extern "C" void kernel_launch(void* const* d_in, const int* in_sizes, int n_in,
                              void* d_out, int out_size) {
    const float* x       = (const float*)d_in[0];
    const float* weight  = (const float*)d_in[1];
    const float* bias    = (const float*)d_in[2];
    const int*   in_idx  = (const int*)d_in[3];
    const int*   out_idx = (const int*)d_in[4];
    float* out = (float*)d_out;

    // pre-pass: gather+round A, zero output (fused), round B
    {
        dim3 g(ACT_IN / 256, NROWS);
        nsl_gather_x<<<g, 256>>>(x, in_idx, (float4*)out);
    }
    nsl_round_w<<<(ACT_OUT * ACT_IN) / 256, 256>>>(weight);

    // tensor-core GEMM (mma.sync) + bias + scatter
    cudaFuncSetAttribute(nsl_mma, cudaFuncAttributeMaxDynamicSharedMemorySize,
                         SMEM_TOTAL);
    dim3 grid(ACT_OUT / BN, NROWS / BM);   // 64 x 32
    nsl_mma<<<grid, NTH, SMEM_TOTAL>>>(bias, out_idx, out);
}